// round 4
// baseline (speedup 1.0000x reference)
#include <cuda_runtime.h>

// GVCNN group pooling collapsed to out[n,c] = sum_v coef[n,gid[n,v]] * RPs[n,v,c].
//
// One WARP per sample, no barriers. Register pressure (the R2 limiter:
// 146 regs -> 15% occ) is cut by staging 16 of the 24 per-lane float4 tile
// chunks in smem: LDG -> dot-FFMA -> STS retires the register immediately;
// the epilogue re-reads them with LDS from the SAME lane-private address
// (same-thread program order => no sync needed). 8 chunks stay in registers.
// __launch_bounds__(128, 6) -> 6 CTAs/SM (24 warps), smem 6x32KB = 192KB.

#define NV 12
#define NBINS 5
#define EPSF 1e-6f

__global__ __launch_bounds__(128, 6) void gvcnn_kernel(
    const float4* __restrict__ RPs4,   // [N, 12, 64] float4
    const float4* __restrict__ w4p,    // [64] float4
    const float*  __restrict__ b,
    float4*       __restrict__ out4)   // [N, 64] float4
{
    const int lane = threadIdx.x & 31;
    const int wrp  = threadIdx.x >> 5;                 // 0..3
    const size_t n = (size_t)blockIdx.x * 4 + wrp;     // sample id

    // [warp][slot][lane]: lanes on fastest dim -> conflict-free LDS/STS.128
    // slots 0..3  = chunk0 (cols lane)    views 8..11
    // slots 4..15 = chunk1 (cols lane+32) views 0..11
    __shared__ float4 s_tile[4][16][32];

    const float4* base = RPs4 + n * (NV * 64) + lane;
    const float4 wa = w4p[lane];
    const float4 wb = w4p[lane + 32];

    float  p[NV];
    float4 rk[8];                                      // kept: chunk0, views 0..7

    // ---- load + dot partials; 16/24 chunks retired to smem immediately ----
#pragma unroll
    for (int v = 0; v < 8; v++) rk[v] = base[v * 64];
#pragma unroll
    for (int v = 0; v < 8; v++)
        p[v] = rk[v].x * wa.x + rk[v].y * wa.y + rk[v].z * wa.z + rk[v].w * wa.w;

#pragma unroll
    for (int v = 8; v < NV; v++) {
        const float4 t = base[v * 64];
        p[v] = t.x * wa.x + t.y * wa.y + t.z * wa.z + t.w * wa.w;
        s_tile[wrp][v - 8][lane] = t;
    }
#pragma unroll
    for (int v = 0; v < NV; v++) {
        const float4 t = base[v * 64 + 32];
        p[v] += t.x * wb.x + t.y * wb.y + t.z * wb.z + t.w * wb.w;
        s_tile[wrp][4 + v][lane] = t;
    }

    // ---- 12 butterfly reductions: full sum lands in every lane ----
#pragma unroll
    for (int off = 16; off > 0; off >>= 1) {
#pragma unroll
        for (int v = 0; v < NV; v++)
            p[v] += __shfl_xor_sync(0xffffffffu, p[v], off);
    }

    // ---- binning logic, redundantly per lane (no broadcast needed) ----
    const float bb = b[0];
    float score[NV];
    int   gid[NV];
#pragma unroll
    for (int v = 0; v < NV; v++) {
        const float x = fabsf(p[v] + bb) + EPSF;
        const float s = x / (1.0f + x);                // == sigmoid(log(x))
        score[v] = s;
        gid[v]   = min((int)(s * 10.0f), 9) >> 1;      // 0..4
    }
    float gsize[NBINS]  = {0.f, 0.f, 0.f, 0.f, 0.f};
    float gscore[NBINS] = {0.f, 0.f, 0.f, 0.f, 0.f};
#pragma unroll
    for (int v = 0; v < NV; v++) gsize[gid[v]] += 1.0f;
#pragma unroll
    for (int v = 0; v < NV; v++)
        gscore[gid[v]] += ceilf(score[v] * gsize[gid[v]]);
    float total = 0.f;
#pragma unroll
    for (int g = 0; g < NBINS; g++) {
        gscore[g] /= (gsize[g] + EPSF);                // reference group_score
        total     += gscore[g];
    }
    const float inv_total = 1.0f / (total + EPSF);

    float cf[NV];
#pragma unroll
    for (int v = 0; v < NV; v++)
        cf[v] = gscore[gid[v]] / (gsize[gid[v]] + EPSF) * inv_total;

    // ---- epilogue: kept registers + lane-private smem re-reads ----
    float4 a0 = make_float4(0.f, 0.f, 0.f, 0.f);
    float4 a1 = make_float4(0.f, 0.f, 0.f, 0.f);
#pragma unroll
    for (int v = 0; v < 8; v++) {
        a0.x += cf[v] * rk[v].x;  a0.y += cf[v] * rk[v].y;
        a0.z += cf[v] * rk[v].z;  a0.w += cf[v] * rk[v].w;
    }
#pragma unroll
    for (int v = 8; v < NV; v++) {
        const float4 t = s_tile[wrp][v - 8][lane];
        a0.x += cf[v] * t.x;  a0.y += cf[v] * t.y;
        a0.z += cf[v] * t.z;  a0.w += cf[v] * t.w;
    }
#pragma unroll
    for (int v = 0; v < NV; v++) {
        const float4 t = s_tile[wrp][4 + v][lane];
        a1.x += cf[v] * t.x;  a1.y += cf[v] * t.y;
        a1.z += cf[v] * t.z;  a1.w += cf[v] * t.w;
    }
    out4[n * 64 + lane]      = a0;
    out4[n * 64 + 32 + lane] = a1;
}

extern "C" void kernel_launch(void* const* d_in, const int* in_sizes, int n_in,
                              void* d_out, int out_size)
{
    const float4* RPs4 = (const float4*)d_in[0];   // [8192,12,256] f32
    const float4* w4p  = (const float4*)d_in[1];   // [256] f32
    const float*  b    = (const float*)d_in[2];    // [1] f32
    float4* out4       = (float4*)d_out;           // [8192,256] f32

    const int n = in_sizes[0] / (NV * 256);        // 8192
    gvcnn_kernel<<<n / 4, 128>>>(RPs4, w4p, b, out4);
}

// round 5
// speedup vs baseline: 2.2072x; 2.2072x over previous
#include <cuda_runtime.h>

// GVCNN group pooling collapsed to out[n,c] = sum_v coef[n,gid[n,v]] * RPs[n,v,c].
//
// One 64-thread block per sample, split BY VIEW across 2 warps:
//   warp h owns views 6h..6h+5; its lane loads float4 chunks {lane, lane+32}
//   of each owned view -> 12 batched coalesced LDG.128 per thread, no
//   dependent ops interleaved (preserves MLP=12; the R4 LDG->STS interleave
//   collapsed MLP and regressed).
//   Each warp's 6 dot products finish fully in-warp (30 SHFL butterflies),
//   y values published to smem, binning computed redundantly per thread with
//   a packed-gid u64 to keep registers ~80 -> 12 CTAs (24 warps)/SM.
//   Epilogue: warp1 drops its view-partial into smem, warp0 adds + stores.

#define NV 12
#define NBINS 5
#define EPSF 1e-6f

__global__ __launch_bounds__(64, 12) void gvcnn_kernel(
    const float4* __restrict__ RPs4,   // [N, 12, 64] float4
    const float4* __restrict__ w4p,    // [64] float4
    const float*  __restrict__ b,
    float4*       __restrict__ out4)   // [N, 64] float4
{
    const int lane = threadIdx.x & 31;
    const int half = threadIdx.x >> 5;          // warp 0 or 1
    const size_t n = blockIdx.x;
    const int v0   = half * 6;                  // first owned view

    __shared__ float  s_y[NV];
    __shared__ float4 s_acc[64];

    const float4* base = RPs4 + n * (NV * 64);
    const float4 wa = w4p[lane];
    const float4 wb = w4p[lane + 32];

    // ---- batched loads: 12 independent coalesced LDG.128, nothing between ----
    float4 r0[6], r1[6];
#pragma unroll
    for (int j = 0; j < 6; j++) {
        r0[j] = base[(v0 + j) * 64 + lane];
        r1[j] = base[(v0 + j) * 64 + 32 + lane];
    }

    // ---- 6 dot partials, reduced fully in-warp (chunks lane + lane+32 cover all 64) ----
    float p[6];
#pragma unroll
    for (int j = 0; j < 6; j++) {
        p[j] = r0[j].x * wa.x + r0[j].y * wa.y + r0[j].z * wa.z + r0[j].w * wa.w
             + r1[j].x * wb.x + r1[j].y * wb.y + r1[j].z * wb.z + r1[j].w * wb.w;
    }
#pragma unroll
    for (int off = 16; off > 0; off >>= 1) {
#pragma unroll
        for (int j = 0; j < 6; j++)
            p[j] += __shfl_xor_sync(0xffffffffu, p[j], off);
    }
    if (lane == 0) {
#pragma unroll
        for (int j = 0; j < 6; j++) s_y[v0 + j] = p[j];
    }
    __syncthreads();

    // ---- binning, redundantly per thread (values identical -> no divergence) ----
    const float bb = b[0];
    unsigned long long pack = 0ull;             // 12 x 3-bit bin ids
    float gsize[NBINS] = {0.f, 0.f, 0.f, 0.f, 0.f};
#pragma unroll
    for (int v = 0; v < NV; v++) {
        const float x = fabsf(s_y[v] + bb) + EPSF;
        const float s = x / (1.0f + x);         // == sigmoid(log(x))
        const int g = min((int)(s * 10.0f), 9) >> 1;
        pack |= (unsigned long long)g << (3 * v);
        gsize[g] += 1.0f;
    }
    float gscore[NBINS] = {0.f, 0.f, 0.f, 0.f, 0.f};
#pragma unroll
    for (int v = 0; v < NV; v++) {
        const float x = fabsf(s_y[v] + bb) + EPSF;
        const float s = x / (1.0f + x);
        const int g = (int)(pack >> (3 * v)) & 7;
        gscore[g] += ceilf(s * gsize[g]);
    }
    float total = 0.f;
#pragma unroll
    for (int g = 0; g < NBINS; g++) {
        gscore[g] /= (gsize[g] + EPSF);         // reference group_score
        total     += gscore[g];
    }
    const float inv_total = 1.0f / (total + EPSF);
    float coef[NBINS];
#pragma unroll
    for (int g = 0; g < NBINS; g++)
        coef[g] = gscore[g] / (gsize[g] + EPSF) * inv_total;

    // ---- per-warp weighted sum over its 6 views (straight from registers) ----
    float4 a0 = make_float4(0.f, 0.f, 0.f, 0.f);
    float4 a1 = make_float4(0.f, 0.f, 0.f, 0.f);
#pragma unroll
    for (int j = 0; j < 6; j++) {
        const int g = (int)(pack >> (3 * (v0 + j))) & 7;
        const float cf = (g == 0) ? coef[0] : (g == 1) ? coef[1] :
                         (g == 2) ? coef[2] : (g == 3) ? coef[3] : coef[4];
        a0.x += cf * r0[j].x;  a0.y += cf * r0[j].y;
        a0.z += cf * r0[j].z;  a0.w += cf * r0[j].w;
        a1.x += cf * r1[j].x;  a1.y += cf * r1[j].y;
        a1.z += cf * r1[j].z;  a1.w += cf * r1[j].w;
    }

    // ---- combine the two view-halves, store coalesced ----
    if (half == 1) {
        s_acc[lane]      = a0;
        s_acc[32 + lane] = a1;
    }
    __syncthreads();
    if (half == 0) {
        const float4 t0 = s_acc[lane];
        const float4 t1 = s_acc[32 + lane];
        a0.x += t0.x;  a0.y += t0.y;  a0.z += t0.z;  a0.w += t0.w;
        a1.x += t1.x;  a1.y += t1.y;  a1.z += t1.z;  a1.w += t1.w;
        out4[n * 64 + lane]      = a0;
        out4[n * 64 + 32 + lane] = a1;
    }
}

extern "C" void kernel_launch(void* const* d_in, const int* in_sizes, int n_in,
                              void* d_out, int out_size)
{
    const float4* RPs4 = (const float4*)d_in[0];   // [8192,12,256] f32
    const float4* w4p  = (const float4*)d_in[1];   // [256] f32
    const float*  b    = (const float*)d_in[2];    // [1] f32
    float4* out4       = (float4*)d_out;           // [8192,256] f32

    const int n = in_sizes[0] / (NV * 256);        // 8192
    gvcnn_kernel<<<n, 64>>>(RPs4, w4p, b, out4);
}

// round 6
// speedup vs baseline: 3.4061x; 1.5431x over previous
#include <cuda_runtime.h>

// GVCNN group pooling collapsed to out[n,c] = sum_v coef[n,gid[n,v]] * RPs[n,v,c].
//
// One 64-thread block per sample, views split across 2 warps (warp h owns
// views 6h..6h+5; each lane holds float4 chunks {lane, lane+32} of its 6
// views -> 12 batched coalesced LDG.128, MLP preserved).
//
// R5 limiter was issue (52%): serial binning (~300 instrs, duplicated in both
// warps). Here binning runs ONCE, warp-parallel in warp 0:
//   lane v<12 owns view v; histogram via match_any+popc (1 instr),
//   per-bin numerator via a 12-step shfl gather (same summation order as
//   before), total via butterfly of gscore_v/gsize_v. Lane v publishes
//   coef[v]; both warps consume 6 coefs each in the register epilogue.

#define NV 12
#define EPSF 1e-6f

__global__ __launch_bounds__(64, 12) void gvcnn_kernel(
    const float4* __restrict__ RPs4,   // [N, 12, 64] float4
    const float4* __restrict__ w4p,    // [64] float4
    const float*  __restrict__ b,
    float4*       __restrict__ out4)   // [N, 64] float4
{
    const int lane = threadIdx.x & 31;
    const int half = threadIdx.x >> 5;          // warp 0 or 1
    const size_t n = blockIdx.x;
    const int v0   = half * 6;                  // first owned view

    __shared__ float  s_y[NV];
    __shared__ float  s_coef[NV];
    __shared__ float4 s_acc[64];

    const float4* base = RPs4 + n * (NV * 64);
    const float4 wa = w4p[lane];
    const float4 wb = w4p[lane + 32];

    // ---- batched loads: 12 independent coalesced LDG.128, nothing between ----
    float4 r0[6], r1[6];
#pragma unroll
    for (int j = 0; j < 6; j++) {
        r0[j] = base[(v0 + j) * 64 + lane];
        r1[j] = base[(v0 + j) * 64 + 32 + lane];
    }

    // ---- 6 dot partials, reduced fully in-warp ----
    float p[6];
#pragma unroll
    for (int j = 0; j < 6; j++) {
        p[j] = r0[j].x * wa.x + r0[j].y * wa.y + r0[j].z * wa.z + r0[j].w * wa.w
             + r1[j].x * wb.x + r1[j].y * wb.y + r1[j].z * wb.z + r1[j].w * wb.w;
    }
#pragma unroll
    for (int off = 16; off > 0; off >>= 1) {
#pragma unroll
        for (int j = 0; j < 6; j++)
            p[j] += __shfl_xor_sync(0xffffffffu, p[j], off);
    }
    if (lane == 0) {
#pragma unroll
        for (int j = 0; j < 6; j++) s_y[v0 + j] = p[j];
    }
    __syncthreads();

    // ---- warp-parallel binning, ONCE per sample (warp 0; lane v owns view v) ----
    if (half == 0) {
        const float bb = b[0];
        const float y  = s_y[lane < NV ? lane : 0];
        const float x  = fabsf(y + bb) + EPSF;
        const float s  = x / (1.0f + x);                 // == sigmoid(log(x))
        const int  gid = min((int)(s * 10.0f), 9) >> 1;  // 0..4

        // bin histogram in one instruction (only view lanes counted)
        const unsigned mask  = __match_any_sync(0xffffffffu, gid) & 0xFFFu;
        const int      gszI  = __popc(mask);             // >=1 for lane<12
        const float    gszF  = (float)(gszI | (gszI == 0)); // guard lanes>=12
        const float    val   = ceilf(s * gszF);

        // numerator: sum of val over matching lanes, increasing-v order
        float numer = 0.f;
#pragma unroll
        for (int u = 0; u < NV; u++) {
            const float vu = __shfl_sync(0xffffffffu, val, u);
            if ((mask >> u) & 1u) numer += vu;
        }
        const float gs = numer / (gszF + EPSF);          // reference group_score

        // total = sum over bins of gs  ==  sum over views of gs/gsize
        float t = (lane < NV) ? gs / gszF : 0.f;
#pragma unroll
        for (int off = 16; off > 0; off >>= 1)
            t += __shfl_xor_sync(0xffffffffu, t, off);

        const float coef = gs / (gszF + EPSF) * (1.0f / (t + EPSF));
        if (lane < NV) s_coef[lane] = coef;
    }
    __syncthreads();

    // ---- register epilogue with this warp's 6 coefficients ----
    float cf[6];
#pragma unroll
    for (int j = 0; j < 6; j++) cf[j] = s_coef[v0 + j];

    float4 a0 = make_float4(0.f, 0.f, 0.f, 0.f);
    float4 a1 = make_float4(0.f, 0.f, 0.f, 0.f);
#pragma unroll
    for (int j = 0; j < 6; j++) {
        a0.x += cf[j] * r0[j].x;  a0.y += cf[j] * r0[j].y;
        a0.z += cf[j] * r0[j].z;  a0.w += cf[j] * r0[j].w;
        a1.x += cf[j] * r1[j].x;  a1.y += cf[j] * r1[j].y;
        a1.z += cf[j] * r1[j].z;  a1.w += cf[j] * r1[j].w;
    }

    // ---- combine the two view-halves, store coalesced ----
    if (half == 1) {
        s_acc[lane]      = a0;
        s_acc[32 + lane] = a1;
    }
    __syncthreads();
    if (half == 0) {
        const float4 t0 = s_acc[lane];
        const float4 t1 = s_acc[32 + lane];
        a0.x += t0.x;  a0.y += t0.y;  a0.z += t0.z;  a0.w += t0.w;
        a1.x += t1.x;  a1.y += t1.y;  a1.z += t1.z;  a1.w += t1.w;
        out4[n * 64 + lane]      = a0;
        out4[n * 64 + 32 + lane] = a1;
    }
}

extern "C" void kernel_launch(void* const* d_in, const int* in_sizes, int n_in,
                              void* d_out, int out_size)
{
    const float4* RPs4 = (const float4*)d_in[0];   // [8192,12,256] f32
    const float4* w4p  = (const float4*)d_in[1];   // [256] f32
    const float*  b    = (const float*)d_in[2];    // [1] f32
    float4* out4       = (float4*)d_out;           // [8192,256] f32

    const int n = in_sizes[0] / (NV * 256);        // 8192
    gvcnn_kernel<<<n, 64>>>(RPs4, w4p, b, out4);
}